// round 15
// baseline (speedup 1.0000x reference)
#include <cuda_runtime.h>
#include <float.h>
#include <math.h>

// Problem constants
#define Bn   4
#define Qn   4
#define Fn   20
#define OBJn 20
#define Dn   4096
#define Mn   1000
#define ROWn (OBJn * Dn)          // 81920 floats per (frame|mem) row
#define BFn  (Bn * Fn)            // 80
#define KSPLIT 32
#define KPER   (Dn / KSPLIT)      // 128 k per block
#define KCHUNK 64                 // k per smem stage (2 stages per block)
#define MPAD 2048
#define OUTBLKS 1184

// gemm dynamic smem: As[64][81] + Bs[64][129]
#define GA_STRIDE 81
#define GB_STRIDE 129
#define GEMM_SMEM ((KCHUNK * GA_STRIDE + KCHUNK * GB_STRIDE) * 4)   // 53,760 B

static const size_t RPN = (size_t)Qn * Bn * Fn * ROWn;   // 26,214,400 elems per big output

// ---------------- device scratch ----------------
__device__ float g_mem_mp[2 * Mn * Dn];          // 32.8 MB: normalized maxpooled mem rows
__device__ float g_rmaxn[BFn * Dn];              // normalized maxpooled R rows
__device__ float g_invnorm[BFn * OBJn];          // per-region inverse norms
__device__ float g_partial[KSPLIT * BFn * MPAD]; // 21 MB k-split partial dots
__device__ int   g_sim[2 * BFn];                 // sim1 (0..79), sim2 (80..159)
__device__ int   g_high[16], g_low[16];          // indexed by b*4+q

// ---------------- helpers ----------------
__device__ __forceinline__ float block_reduce_sum(float v) {
    __shared__ float sh[32];
    __shared__ float res;
    int lane = threadIdx.x & 31, w = threadIdx.x >> 5;
#pragma unroll
    for (int o = 16; o; o >>= 1) v += __shfl_down_sync(0xffffffffu, v, o);
    __syncthreads();
    if (!lane) sh[w] = v;
    __syncthreads();
    if (w == 0) {
        float x = (lane < (int)(blockDim.x >> 5)) ? sh[lane] : 0.f;
#pragma unroll
        for (int o = 16; o; o >>= 1) x += __shfl_down_sync(0xffffffffu, x, o);
        if (!lane) res = x;
    }
    __syncthreads();
    return res;
}

__device__ __forceinline__ float4 fmax4(float4 a, float4 b) {
    a.x = fmaxf(a.x, b.x); a.y = fmaxf(a.y, b.y);
    a.z = fmaxf(a.z, b.z); a.w = fmaxf(a.w, b.w);
    return a;
}

// ---------------- K_sel ----------------
__global__ void k_sel(const float* __restrict__ qr, const int* __restrict__ rnd) {
    int t = threadIdx.x;
    if (t >= 16) return;
    int b = t >> 2, q = t & 3;                // t = b*4 + q
    const float* w = qr + (b * Qn + q) * Fn;
    int hi = 0; float hv = w[0];
    for (int f = 1; f < Fn; f++) if (w[f] > hv) { hv = w[f]; hi = f; }
    int rr = rnd[b * Qn + q];
    int lo = 0;
    for (int i = 0; i < Fn; i++) {
        int rank = 0;
        for (int j = 0; j < Fn; j++)
            rank += (w[j] < w[i]) || (w[j] == w[i] && j < i);
        if (rank == rr) { lo = i; break; }
    }
    g_high[t] = hi; g_low[t] = lo;
}

// ---------------- K_rstats ----------------
__global__ __launch_bounds__(256) void k_rstats(const float* __restrict__ inp) {
    int bf = blockIdx.x;
    const float* base = inp + (size_t)bf * ROWn;
    float4 mx[4];
#pragma unroll
    for (int i = 0; i < 4; i++) mx[i] = make_float4(-FLT_MAX, -FLT_MAX, -FLT_MAX, -FLT_MAX);
    for (int o = 0; o < OBJn; o++) {
        float4 x[4];
        const float4* p = (const float4*)(base + (size_t)o * Dn);
        float s = 0.f;
#pragma unroll
        for (int i = 0; i < 4; i++) {
            x[i] = p[threadIdx.x + i * 256];
            s += x[i].x * x[i].x + x[i].y * x[i].y + x[i].z * x[i].z + x[i].w * x[i].w;
        }
        s = block_reduce_sum(s);
        float inv = 1.f / fmaxf(sqrtf(s), 1e-12f);
        if (threadIdx.x == 0) g_invnorm[bf * OBJn + o] = inv;
#pragma unroll
        for (int i = 0; i < 4; i++) {
            float4 v = x[i];
            v.x *= inv; v.y *= inv; v.z *= inv; v.w *= inv;
            mx[i] = fmax4(mx[i], v);
        }
    }
    float s2 = 0.f;
#pragma unroll
    for (int i = 0; i < 4; i++)
        s2 += mx[i].x * mx[i].x + mx[i].y * mx[i].y + mx[i].z * mx[i].z + mx[i].w * mx[i].w;
    s2 = block_reduce_sum(s2);
    float inv2 = 1.f / fmaxf(sqrtf(s2), 1e-12f);
    float4* out = (float4*)(g_rmaxn + (size_t)bf * Dn);
#pragma unroll
    for (int i = 0; i < 4; i++) {
        float4 v = mx[i];
        v.x *= inv2; v.y *= inv2; v.z *= inv2; v.w *= inv2;
        out[threadIdx.x + i * 256] = v;
    }
}

// ---------------- K_mem_mp (proven at DRAM floor) ----------------
__global__ __launch_bounds__(256) void k_mem_mp(const float* __restrict__ mem1,
                                                const float* __restrict__ mem2) {
    int row = blockIdx.x;
    const float* src = (row >= Mn) ? (mem2 + (size_t)(row - Mn) * ROWn)
                                   : (mem1 + (size_t)row * ROWn);
    float4 mx[4];
#pragma unroll
    for (int i = 0; i < 4; i++) mx[i] = make_float4(-FLT_MAX, -FLT_MAX, -FLT_MAX, -FLT_MAX);
    for (int o = 0; o < OBJn; o++) {
        const float4* p = (const float4*)(src + (size_t)o * Dn);
#pragma unroll
        for (int i = 0; i < 4; i++) mx[i] = fmax4(mx[i], p[threadIdx.x + i * 256]);
    }
    float s = 0.f;
#pragma unroll
    for (int i = 0; i < 4; i++)
        s += mx[i].x * mx[i].x + mx[i].y * mx[i].y + mx[i].z * mx[i].z + mx[i].w * mx[i].w;
    s = block_reduce_sum(s);
    float inv = 1.f / fmaxf(sqrtf(s), 1e-12f);
    float4* out = (float4*)(g_mem_mp + (size_t)row * Dn);
#pragma unroll
    for (int i = 0; i < 4; i++) {
        float4 v = mx[i];
        v.x *= inv; v.y *= inv; v.z *= inv; v.w *= inv;
        out[threadIdx.x + i * 256] = v;
    }
}

// ---------------- K_gemm v4: 64-wide k chunks, half the barriers ---------------------
// grid (16 m-tiles of 128, 32 k-splits of 128), 256 threads, 4 blocks/SM (smem+regs).
__global__ __launch_bounds__(256, 4) void k_gemm() {
    extern __shared__ float gsm[];
    float* As = gsm;                          // [KCHUNK][81]  [kk][r]
    float* Bs = gsm + KCHUNK * GA_STRIDE;     // [KCHUNK][129] [kk][m]
    int tid = threadIdx.x;
    int tx = tid & 15;              // m group: 8 each -> 128
    int ty = tid >> 4;              // r group: 5 each -> 80
    int m0 = blockIdx.x * 128;
    int kbase = blockIdx.y * KPER;

    float acc[5][8];
#pragma unroll
    for (int i = 0; i < 5; i++)
#pragma unroll
        for (int j = 0; j < 8; j++) acc[i][j] = 0.f;

    for (int kc = 0; kc < KPER / KCHUNK; kc++) {      // 2 chunks
        int k0 = kbase + kc * KCHUNK;
        __syncthreads();
        // A tile: 80 r x 64 k, transposed store (bank=(4c4+17j+r)%32, conflict-free)
        for (int idx = tid; idx < 80 * (KCHUNK / 4); idx += 256) {
            int r = idx >> 4, c4 = idx & 15;
            float4 v = *(const float4*)(g_rmaxn + (size_t)r * Dn + k0 + c4 * 4);
            As[(c4 * 4 + 0) * GA_STRIDE + r] = v.x;
            As[(c4 * 4 + 1) * GA_STRIDE + r] = v.y;
            As[(c4 * 4 + 2) * GA_STRIDE + r] = v.z;
            As[(c4 * 4 + 3) * GA_STRIDE + r] = v.w;
        }
        // B tile: 128 m x 64 k, transposed store (bank=(4c4+j+m)%32, conflict-free)
#pragma unroll
        for (int l = 0; l < 8; l++) {
            int idx = tid + l * 256;
            int m = idx >> 4, c4 = idx & 15;
            int mg = m0 + m;
            float4 v = make_float4(0.f, 0.f, 0.f, 0.f);
            if (mg < 2 * Mn)
                v = *(const float4*)(g_mem_mp + (size_t)mg * Dn + k0 + c4 * 4);
            Bs[(c4 * 4 + 0) * GB_STRIDE + m] = v.x;
            Bs[(c4 * 4 + 1) * GB_STRIDE + m] = v.y;
            Bs[(c4 * 4 + 2) * GB_STRIDE + m] = v.z;
            Bs[(c4 * 4 + 3) * GB_STRIDE + m] = v.w;
        }
        __syncthreads();
#pragma unroll 16
        for (int kk = 0; kk < KCHUNK; kk++) {
            float a[5], b[8];
#pragma unroll
            for (int i = 0; i < 5; i++) a[i] = As[kk * GA_STRIDE + ty * 5 + i];
#pragma unroll
            for (int j = 0; j < 8; j++) b[j] = Bs[kk * GB_STRIDE + tx * 8 + j];
#pragma unroll
            for (int i = 0; i < 5; i++)
#pragma unroll
                for (int j = 0; j < 8; j++) acc[i][j] = fmaf(a[i], b[j], acc[i][j]);
        }
    }
    // vectorized partial store
    float* dst = g_partial + (size_t)blockIdx.y * BFn * MPAD;
#pragma unroll
    for (int i = 0; i < 5; i++) {
        float4* p = (float4*)(dst + (ty * 5 + i) * MPAD + m0 + tx * 8);
        p[0] = make_float4(acc[i][0], acc[i][1], acc[i][2], acc[i][3]);
        p[1] = make_float4(acc[i][4], acc[i][5], acc[i][6], acc[i][7]);
    }
}

// ---------------- K_argmax: one block per (row, mem-half) ----------------
__global__ __launch_bounds__(512) void k_argmax() {
    int r = blockIdx.x >> 1;
    int h = blockIdx.x & 1;
    int tid = threadIdx.x;
    float bv = -FLT_MAX;
    int   bm = 0;
    for (int m = tid; m < Mn; m += 512) {
        int mg = h * Mn + m;
        float s = 0.f;
#pragma unroll
        for (int ks = 0; ks < KSPLIT; ks++)
            s += g_partial[(size_t)ks * BFn * MPAD + (size_t)r * MPAD + mg];
        if (s > bv || (s == bv && m < bm)) { bv = s; bm = m; }
    }
    __shared__ float sv[512];
    __shared__ int   sm2[512];
    sv[tid] = bv; sm2[tid] = bm;
    __syncthreads();
    for (int st = 256; st; st >>= 1) {
        if (tid < st) {
            float ov = sv[tid + st]; int om = sm2[tid + st];
            if (ov > sv[tid] || (ov == sv[tid] && om < sm2[tid])) {
                sv[tid] = ov; sm2[tid] = om;
            }
        }
        __syncthreads();
    }
    if (tid == 0) g_sim[h * BFn + r] = sm2[0];
}

// ---------------- K_out: all output writes (R10-proven 41us) ----------------
#define FILL_ITEMS (BFn * 80)                 // 6400
#define REPL_ITEMS (32 * 16)                  // 512
#define NITEMS     (FILL_ITEMS + REPL_ITEMS + 1)

__global__ __launch_bounds__(256) void k_out(const float* __restrict__ inp,
                                             const float* __restrict__ mem1,
                                             const float* __restrict__ mem2,
                                             float* __restrict__ out,
                                             long long out_size) {
    int tid = threadIdx.x;
    float4* o4 = (float4*)out;
    const size_t rpn4 = RPN / 4;
    for (int it = blockIdx.x; it < NITEMS; it += gridDim.x) {
        if (it < FILL_ITEMS) {
            int bf = it / 80;
            int ch = it % 80;
            int b = bf / Fn, f = bf % Fn;
            int e4 = ch * 256 + tid;
            int oo = e4 >> 10;
            float inv = g_invnorm[bf * OBJn + oo];
            float4 v = ((const float4*)(inp + (size_t)bf * ROWn))[e4];
            v.x *= inv; v.y *= inv; v.z *= inv; v.w *= inv;
#pragma unroll
            for (int q = 0; q < 4; q++) {
                int lo = g_low[b * 4 + q], hi = g_high[b * 4 + q];
                size_t ob = ((size_t)((q * Bn + b) * Fn + f)) * (ROWn / 4) + e4;
                if (f != lo) o4[ob] = v;            // Rp copy
                if (f != hi) o4[rpn4 + ob] = v;     // Rn copy
            }
        } else if (it < FILL_ITEMS + REPL_ITEMS) {
            int ri = it - FILL_ITEMS;
            int t2 = ri / 16;
            int ch = ri % 16;
            int which = t2 & 1;                // 0: Rp/low/mem1  1: Rn/high/mem2
            int bq = t2 >> 1;
            int b = bq >> 2, q = bq & 3;
            int lo = g_low[bq];
            int f, row;
            const float* src;
            if (which == 0) { f = lo;         row = g_sim[b * Fn + lo];       src = mem1; }
            else            { f = g_high[bq]; row = g_sim[BFn + b * Fn + lo]; src = mem2; }
            const float4* s4 = (const float4*)(src + (size_t)row * ROWn);
            float4* d4 = (float4*)(out + (size_t)which * RPN +
                                   ((size_t)((q * Bn + b) * Fn + f)) * ROWn);
            int base = ch * 1280;
#pragma unroll
            for (int i = 0; i < 5; i++) {
                int e4 = base + tid + i * 256;
                d4[e4] = s4[e4];
            }
        } else {
            if (tid < 16) {
                int bq = tid;
                int b = bq >> 2, q = bq & 3;
                long long rpn2 = (long long)(2 * RPN);
                if (out_size >= rpn2 + 32) {
                    out[(size_t)rpn2 + (q * Bn + b)]      =
                        (float)g_sim[BFn + b * Fn + g_high[bq]];   // high_sim
                    out[(size_t)rpn2 + 16 + (q * Bn + b)] =
                        (float)g_sim[b * Fn + g_low[bq]];          // low_sim
                }
            }
        }
    }
}

// ---------------- launch: strictly serial, deterministic ----------------
extern "C" void kernel_launch(void* const* d_in, const int* in_sizes, int n_in,
                              void* d_out, int out_size) {
    const float* qr   = (const float*)d_in[0];   // [4,4,20]
    const float* inp  = (const float*)d_in[1];   // [4,20,20,4096]
    const float* mem1 = (const float*)d_in[2];   // [1000,81920]
    const float* mem2 = (const float*)d_in[3];   // [1000,81920]
    const int*   rnd  = (const int*)d_in[4];     // [4,4,1]
    float* out = (float*)d_out;

    // opt into 53.8 KB dynamic smem for the gemm (idempotent, capture-safe)
    cudaFuncSetAttribute((const void*)k_gemm,
                         cudaFuncAttributeMaxDynamicSharedMemorySize, GEMM_SMEM);

    k_sel<<<1, 32>>>(qr, rnd);                   // ~1us
    k_rstats<<<BFn, 256>>>(inp);                 // ~6us
    k_mem_mp<<<2 * Mn, 256>>>(mem1, mem2);       // ~100us (DRAM floor)
    k_gemm<<<dim3(16, KSPLIT), 256, GEMM_SMEM>>>();   // target <55us
    k_argmax<<<2 * BFn, 512>>>();                // ~5us
    k_out<<<OUTBLKS, 256>>>(inp, mem1, mem2, out, (long long)out_size);  // ~41us
}

// round 16
// speedup vs baseline: 1.0585x; 1.0585x over previous
#include <cuda_runtime.h>
#include <float.h>
#include <math.h>

// Problem constants
#define Bn   4
#define Qn   4
#define Fn   20
#define OBJn 20
#define Dn   4096
#define Mn   1000
#define ROWn (OBJn * Dn)          // 81920 floats per (frame|mem) row
#define BFn  (Bn * Fn)            // 80
#define KSPLIT 32
#define KPER   (Dn / KSPLIT)      // 128 k per block
#define KCHUNK 64                 // k per smem stage
#define MPAD 2048

// gemm dynamic smem: As[64][81] + Bs[64][129]
#define GA_STRIDE 81
#define GB_STRIDE 129
#define GEMM_SMEM ((KCHUNK * GA_STRIDE + KCHUNK * GB_STRIDE) * 4)   // 53,760 B

#define GEMM_BLKS 512             // 16 m-tiles x 32 k-splits, scheduled first
#define FILL_BLKS 1184
#define FILL_ITEMS (BFn * 80)     // 6400 items of 256 float4

static const size_t RPN = (size_t)Qn * Bn * Fn * ROWn;   // 26,214,400 elems per big output

// ---------------- device scratch ----------------
__device__ float g_mem_mp[2 * Mn * Dn];          // 32.8 MB: normalized maxpooled mem rows
__device__ float g_rmaxn[BFn * Dn];              // normalized maxpooled R rows
__device__ float g_invnorm[BFn * OBJn];          // per-region inverse norms
__device__ float g_partial[KSPLIT * BFn * MPAD]; // 21 MB k-split partial dots
__device__ int   g_sim[2 * BFn];                 // sim1 (0..79), sim2 (80..159)
__device__ int   g_high[16], g_low[16];          // indexed by b*4+q

// ---------------- helpers ----------------
__device__ __forceinline__ float block_reduce_sum(float v) {
    __shared__ float sh[32];
    __shared__ float res;
    int lane = threadIdx.x & 31, w = threadIdx.x >> 5;
#pragma unroll
    for (int o = 16; o; o >>= 1) v += __shfl_down_sync(0xffffffffu, v, o);
    __syncthreads();
    if (!lane) sh[w] = v;
    __syncthreads();
    if (w == 0) {
        float x = (lane < (int)(blockDim.x >> 5)) ? sh[lane] : 0.f;
#pragma unroll
        for (int o = 16; o; o >>= 1) x += __shfl_down_sync(0xffffffffu, x, o);
        if (!lane) res = x;
    }
    __syncthreads();
    return res;
}

__device__ __forceinline__ float4 fmax4(float4 a, float4 b) {
    a.x = fmaxf(a.x, b.x); a.y = fmaxf(a.y, b.y);
    a.z = fmaxf(a.z, b.z); a.w = fmaxf(a.w, b.w);
    return a;
}

// ---------------- K_sel ----------------
__global__ void k_sel(const float* __restrict__ qr, const int* __restrict__ rnd) {
    int t = threadIdx.x;
    if (t >= 16) return;
    int b = t >> 2, q = t & 3;                // t = b*4 + q
    const float* w = qr + (b * Qn + q) * Fn;
    int hi = 0; float hv = w[0];
    for (int f = 1; f < Fn; f++) if (w[f] > hv) { hv = w[f]; hi = f; }
    int rr = rnd[b * Qn + q];
    int lo = 0;
    for (int i = 0; i < Fn; i++) {
        int rank = 0;
        for (int j = 0; j < Fn; j++)
            rank += (w[j] < w[i]) || (w[j] == w[i] && j < i);
        if (rank == rr) { lo = i; break; }
    }
    g_high[t] = hi; g_low[t] = lo;
}

// ---------------- K_rstats ----------------
__global__ __launch_bounds__(256) void k_rstats(const float* __restrict__ inp) {
    int bf = blockIdx.x;
    const float* base = inp + (size_t)bf * ROWn;
    float4 mx[4];
#pragma unroll
    for (int i = 0; i < 4; i++) mx[i] = make_float4(-FLT_MAX, -FLT_MAX, -FLT_MAX, -FLT_MAX);
    for (int o = 0; o < OBJn; o++) {
        float4 x[4];
        const float4* p = (const float4*)(base + (size_t)o * Dn);
        float s = 0.f;
#pragma unroll
        for (int i = 0; i < 4; i++) {
            x[i] = p[threadIdx.x + i * 256];
            s += x[i].x * x[i].x + x[i].y * x[i].y + x[i].z * x[i].z + x[i].w * x[i].w;
        }
        s = block_reduce_sum(s);
        float inv = 1.f / fmaxf(sqrtf(s), 1e-12f);
        if (threadIdx.x == 0) g_invnorm[bf * OBJn + o] = inv;
#pragma unroll
        for (int i = 0; i < 4; i++) {
            float4 v = x[i];
            v.x *= inv; v.y *= inv; v.z *= inv; v.w *= inv;
            mx[i] = fmax4(mx[i], v);
        }
    }
    float s2 = 0.f;
#pragma unroll
    for (int i = 0; i < 4; i++)
        s2 += mx[i].x * mx[i].x + mx[i].y * mx[i].y + mx[i].z * mx[i].z + mx[i].w * mx[i].w;
    s2 = block_reduce_sum(s2);
    float inv2 = 1.f / fmaxf(sqrtf(s2), 1e-12f);
    float4* out = (float4*)(g_rmaxn + (size_t)bf * Dn);
#pragma unroll
    for (int i = 0; i < 4; i++) {
        float4 v = mx[i];
        v.x *= inv2; v.y *= inv2; v.z *= inv2; v.w *= inv2;
        out[threadIdx.x + i * 256] = v;
    }
}

// ---------------- K_mem_mp (proven at DRAM floor) ----------------
__global__ __launch_bounds__(256) void k_mem_mp(const float* __restrict__ mem1,
                                                const float* __restrict__ mem2) {
    int row = blockIdx.x;
    const float* src = (row >= Mn) ? (mem2 + (size_t)(row - Mn) * ROWn)
                                   : (mem1 + (size_t)row * ROWn);
    float4 mx[4];
#pragma unroll
    for (int i = 0; i < 4; i++) mx[i] = make_float4(-FLT_MAX, -FLT_MAX, -FLT_MAX, -FLT_MAX);
    for (int o = 0; o < OBJn; o++) {
        const float4* p = (const float4*)(src + (size_t)o * Dn);
#pragma unroll
        for (int i = 0; i < 4; i++) mx[i] = fmax4(mx[i], p[threadIdx.x + i * 256]);
    }
    float s = 0.f;
#pragma unroll
    for (int i = 0; i < 4; i++)
        s += mx[i].x * mx[i].x + mx[i].y * mx[i].y + mx[i].z * mx[i].z + mx[i].w * mx[i].w;
    s = block_reduce_sum(s);
    float inv = 1.f / fmaxf(sqrtf(s), 1e-12f);
    float4* out = (float4*)(g_mem_mp + (size_t)row * Dn);
#pragma unroll
    for (int i = 0; i < 4; i++) {
        float4 v = mx[i];
        v.x *= inv; v.y *= inv; v.z *= inv; v.w *= inv;
        out[threadIdx.x + i * 256] = v;
    }
}

// ---------------- K_main: gemm blocks [0,512) + fill blocks [512,1696) ---------------
// gemm: issue-bound (66us);  fill: DRAM-bound (41us of traffic) — complementary pipes.
// gemm reads each B element exactly once (no L2 reuse), so fill's stream can't evict
// anything that matters. R7 evidence: merged kernel ran at max() of the two, not sum.
__global__ __launch_bounds__(256, 4) void k_main(const float* __restrict__ inp,
                                                 float* __restrict__ out) {
    int tid = threadIdx.x;
    if (blockIdx.x < GEMM_BLKS) {
        // ---- gemm v4 (measured 66us standalone) ----
        extern __shared__ float gsm[];
        float* As = gsm;                          // [KCHUNK][81]  [kk][r]
        float* Bs = gsm + KCHUNK * GA_STRIDE;     // [KCHUNK][129] [kk][m]
        int tx = tid & 15;              // m group: 8 each -> 128
        int ty = tid >> 4;              // r group: 5 each -> 80
        int m0 = (blockIdx.x & 15) * 128;
        int ks = blockIdx.x >> 4;
        int kbase = ks * KPER;

        float acc[5][8];
#pragma unroll
        for (int i = 0; i < 5; i++)
#pragma unroll
            for (int j = 0; j < 8; j++) acc[i][j] = 0.f;

        for (int kc = 0; kc < KPER / KCHUNK; kc++) {      // 2 chunks
            int k0 = kbase + kc * KCHUNK;
            __syncthreads();
            for (int idx = tid; idx < 80 * (KCHUNK / 4); idx += 256) {
                int r = idx >> 4, c4 = idx & 15;
                float4 v = *(const float4*)(g_rmaxn + (size_t)r * Dn + k0 + c4 * 4);
                As[(c4 * 4 + 0) * GA_STRIDE + r] = v.x;
                As[(c4 * 4 + 1) * GA_STRIDE + r] = v.y;
                As[(c4 * 4 + 2) * GA_STRIDE + r] = v.z;
                As[(c4 * 4 + 3) * GA_STRIDE + r] = v.w;
            }
#pragma unroll
            for (int l = 0; l < 8; l++) {
                int idx = tid + l * 256;
                int m = idx >> 4, c4 = idx & 15;
                int mg = m0 + m;
                float4 v = make_float4(0.f, 0.f, 0.f, 0.f);
                if (mg < 2 * Mn)
                    v = *(const float4*)(g_mem_mp + (size_t)mg * Dn + k0 + c4 * 4);
                Bs[(c4 * 4 + 0) * GB_STRIDE + m] = v.x;
                Bs[(c4 * 4 + 1) * GB_STRIDE + m] = v.y;
                Bs[(c4 * 4 + 2) * GB_STRIDE + m] = v.z;
                Bs[(c4 * 4 + 3) * GB_STRIDE + m] = v.w;
            }
            __syncthreads();
#pragma unroll 16
            for (int kk = 0; kk < KCHUNK; kk++) {
                float a[5], b[8];
#pragma unroll
                for (int i = 0; i < 5; i++) a[i] = As[kk * GA_STRIDE + ty * 5 + i];
#pragma unroll
                for (int j = 0; j < 8; j++) b[j] = Bs[kk * GB_STRIDE + tx * 8 + j];
#pragma unroll
                for (int i = 0; i < 5; i++)
#pragma unroll
                    for (int j = 0; j < 8; j++) acc[i][j] = fmaf(a[i], b[j], acc[i][j]);
            }
        }
        float* dst = g_partial + (size_t)ks * BFn * MPAD;
#pragma unroll
        for (int i = 0; i < 5; i++) {
            float4* p = (float4*)(dst + (ty * 5 + i) * MPAD + m0 + tx * 8);
            p[0] = make_float4(acc[i][0], acc[i][1], acc[i][2], acc[i][3]);
            p[1] = make_float4(acc[i][4], acc[i][5], acc[i][6], acc[i][7]);
        }
    } else {
        // ---- fill: grid-stride over 6400 items (normalize + fan-out) ----
        int fb = blockIdx.x - GEMM_BLKS;
        int nfb = gridDim.x - GEMM_BLKS;
        float4* o4 = (float4*)out;
        const size_t rpn4 = RPN / 4;
        for (int it = fb; it < FILL_ITEMS; it += nfb) {
            int bf = it / 80;
            int ch = it % 80;
            int b = bf / Fn, f = bf % Fn;
            int e4 = ch * 256 + tid;
            int oo = e4 >> 10;
            float inv = g_invnorm[bf * OBJn + oo];
            float4 v = ((const float4*)(inp + (size_t)bf * ROWn))[e4];
            v.x *= inv; v.y *= inv; v.z *= inv; v.w *= inv;
#pragma unroll
            for (int q = 0; q < 4; q++) {
                int lo = g_low[b * 4 + q], hi = g_high[b * 4 + q];
                size_t ob = ((size_t)((q * Bn + b) * Fn + f)) * (ROWn / 4) + e4;
                if (f != lo) o4[ob] = v;            // Rp copy
                if (f != hi) o4[rpn4 + ob] = v;     // Rn copy
            }
        }
    }
}

// ---------------- K_argmax: one block per (row, mem-half) ----------------
__global__ __launch_bounds__(512) void k_argmax() {
    int r = blockIdx.x >> 1;
    int h = blockIdx.x & 1;
    int tid = threadIdx.x;
    float bv = -FLT_MAX;
    int   bm = 0;
    for (int m = tid; m < Mn; m += 512) {
        int mg = h * Mn + m;
        float s = 0.f;
#pragma unroll
        for (int ks = 0; ks < KSPLIT; ks++)
            s += g_partial[(size_t)ks * BFn * MPAD + (size_t)r * MPAD + mg];
        if (s > bv || (s == bv && m < bm)) { bv = s; bm = m; }
    }
    __shared__ float sv[512];
    __shared__ int   sm2[512];
    sv[tid] = bv; sm2[tid] = bm;
    __syncthreads();
    for (int st = 256; st; st >>= 1) {
        if (tid < st) {
            float ov = sv[tid + st]; int om = sm2[tid + st];
            if (ov > sv[tid] || (ov == sv[tid] && om < sm2[tid])) {
                sv[tid] = ov; sm2[tid] = om;
            }
        }
        __syncthreads();
    }
    if (tid == 0) g_sim[h * BFn + r] = sm2[0];
}

// ---------------- K_replace: replaced rows + sim outputs (needs g_sim) ---------------
// grid (33, 16) x 256; x<32: copy mem rows (chunk y); x==32 (y==0): write sims.
__global__ __launch_bounds__(256) void k_replace(const float* __restrict__ mem1,
                                                 const float* __restrict__ mem2,
                                                 float* __restrict__ out,
                                                 long long out_size) {
    int t = blockIdx.x;
    if (t == 32) {
        if (blockIdx.y == 0 && threadIdx.x < 16) {
            int bq = threadIdx.x;               // b*4 + q
            int b = bq >> 2, q = bq & 3;
            long long rpn2 = (long long)(2 * RPN);
            if (out_size >= rpn2 + 32) {
                out[(size_t)rpn2 + (q * Bn + b)]      =
                    (float)g_sim[BFn + b * Fn + g_high[bq]];   // high_sim
                out[(size_t)rpn2 + 16 + (q * Bn + b)] =
                    (float)g_sim[b * Fn + g_low[bq]];          // low_sim
            }
        }
        return;
    }
    int which = t & 1;         // 0: Rp/low/mem1   1: Rn/high/mem2
    int bq = t >> 1;           // b*4 + q
    int b = bq >> 2, q = bq & 3;
    int f, row;
    const float* src;
    int lo = g_low[bq];
    if (which == 0) { f = lo;         row = g_sim[b * Fn + lo];       src = mem1; }
    else            { f = g_high[bq]; row = g_sim[BFn + b * Fn + lo]; src = mem2; }
    const float4* s4 = (const float4*)(src + (size_t)row * ROWn);
    float4* d4 = (float4*)(out + (size_t)which * RPN +
                           ((size_t)((q * Bn + b) * Fn + f)) * ROWn);
    int base = blockIdx.y * 1280;              // 16 chunks of 1280 float4
#pragma unroll
    for (int i = 0; i < 5; i++) {
        int e4 = base + threadIdx.x + i * 256;
        d4[e4] = s4[e4];
    }
}

// ---------------- launch: strictly serial, deterministic ----------------
extern "C" void kernel_launch(void* const* d_in, const int* in_sizes, int n_in,
                              void* d_out, int out_size) {
    const float* qr   = (const float*)d_in[0];   // [4,4,20]
    const float* inp  = (const float*)d_in[1];   // [4,20,20,4096]
    const float* mem1 = (const float*)d_in[2];   // [1000,81920]
    const float* mem2 = (const float*)d_in[3];   // [1000,81920]
    const int*   rnd  = (const int*)d_in[4];     // [4,4,1]
    float* out = (float*)d_out;

    // opt into 53.8 KB dynamic smem for k_main (idempotent, capture-safe)
    cudaFuncSetAttribute((const void*)k_main,
                         cudaFuncAttributeMaxDynamicSharedMemorySize, GEMM_SMEM);

    k_sel<<<1, 32>>>(qr, rnd);                               // ~1us
    k_rstats<<<BFn, 256>>>(inp);                             // ~6us
    k_mem_mp<<<2 * Mn, 256>>>(mem1, mem2);                   // ~100us (DRAM floor)
    k_main<<<GEMM_BLKS + FILL_BLKS, 256, GEMM_SMEM>>>(inp, out);  // ~max(gemm, fill)
    k_argmax<<<2 * BFn, 512>>>();                            // ~5us
    k_replace<<<dim3(33, 16), 256>>>(mem1, mem2, out, (long long)out_size);  // ~8us
}

// round 17
// speedup vs baseline: 1.0756x; 1.0161x over previous
#include <cuda_runtime.h>
#include <float.h>
#include <math.h>

// Problem constants
#define Bn   4
#define Qn   4
#define Fn   20
#define OBJn 20
#define Dn   4096
#define Mn   1000
#define ROWn (OBJn * Dn)          // 81920 floats per (frame|mem) row
#define BFn  (Bn * Fn)            // 80
#define KSPLIT 32
#define KPER   (Dn / KSPLIT)      // 128 k per block
#define KCHUNK 64                 // k per smem stage
#define MPAD 2048

// gemm dynamic smem: As[64][81] + Bs[64][129]
#define GA_STRIDE 81
#define GB_STRIDE 129
#define GEMM_SMEM ((KCHUNK * GA_STRIDE + KCHUNK * GB_STRIDE) * 4)   // 53,760 B

#define GEMM_BLKS 512             // 16 m-tiles x 32 k-splits, scheduled first
#define FILL_BLKS 1184
#define FILL_ITEMS (BFn * 80)     // 6400 items of 256 float4

static const size_t RPN = (size_t)Qn * Bn * Fn * ROWn;   // 26,214,400 elems per big output

// ---------------- device scratch ----------------
__device__ float g_mem_mp[2 * Mn * Dn];          // 32.8 MB: normalized maxpooled mem rows
__device__ float g_rmaxn[BFn * Dn];              // normalized maxpooled R rows
__device__ float g_invnorm[BFn * OBJn];          // per-region inverse norms
__device__ float g_partial[KSPLIT * BFn * MPAD]; // 21 MB k-split partial dots
__device__ int   g_sim[2 * BFn];                 // sim1 (0..79), sim2 (80..159)
__device__ int   g_high[16], g_low[16];          // indexed by b*4+q

// ---------------- helpers ----------------
__device__ __forceinline__ float block_reduce_sum(float v) {
    __shared__ float sh[32];
    __shared__ float res;
    int lane = threadIdx.x & 31, w = threadIdx.x >> 5;
#pragma unroll
    for (int o = 16; o; o >>= 1) v += __shfl_down_sync(0xffffffffu, v, o);
    __syncthreads();
    if (!lane) sh[w] = v;
    __syncthreads();
    if (w == 0) {
        float x = (lane < (int)(blockDim.x >> 5)) ? sh[lane] : 0.f;
#pragma unroll
        for (int o = 16; o; o >>= 1) x += __shfl_down_sync(0xffffffffu, x, o);
        if (!lane) res = x;
    }
    __syncthreads();
    return res;
}

__device__ __forceinline__ float4 fmax4(float4 a, float4 b) {
    a.x = fmaxf(a.x, b.x); a.y = fmaxf(a.y, b.y);
    a.z = fmaxf(a.z, b.z); a.w = fmaxf(a.w, b.w);
    return a;
}

// ---------------- K_sel ----------------
__global__ void k_sel(const float* __restrict__ qr, const int* __restrict__ rnd) {
    int t = threadIdx.x;
    if (t >= 16) return;
    int b = t >> 2, q = t & 3;                // t = b*4 + q
    const float* w = qr + (b * Qn + q) * Fn;
    int hi = 0; float hv = w[0];
    for (int f = 1; f < Fn; f++) if (w[f] > hv) { hv = w[f]; hi = f; }
    int rr = rnd[b * Qn + q];
    int lo = 0;
    for (int i = 0; i < Fn; i++) {
        int rank = 0;
        for (int j = 0; j < Fn; j++)
            rank += (w[j] < w[i]) || (w[j] == w[i] && j < i);
        if (rank == rr) { lo = i; break; }
    }
    g_high[t] = hi; g_low[t] = lo;
}

// ---------------- K_rstats ----------------
__global__ __launch_bounds__(256) void k_rstats(const float* __restrict__ inp) {
    int bf = blockIdx.x;
    const float* base = inp + (size_t)bf * ROWn;
    float4 mx[4];
#pragma unroll
    for (int i = 0; i < 4; i++) mx[i] = make_float4(-FLT_MAX, -FLT_MAX, -FLT_MAX, -FLT_MAX);
    for (int o = 0; o < OBJn; o++) {
        float4 x[4];
        const float4* p = (const float4*)(base + (size_t)o * Dn);
        float s = 0.f;
#pragma unroll
        for (int i = 0; i < 4; i++) {
            x[i] = p[threadIdx.x + i * 256];
            s += x[i].x * x[i].x + x[i].y * x[i].y + x[i].z * x[i].z + x[i].w * x[i].w;
        }
        s = block_reduce_sum(s);
        float inv = 1.f / fmaxf(sqrtf(s), 1e-12f);
        if (threadIdx.x == 0) g_invnorm[bf * OBJn + o] = inv;
#pragma unroll
        for (int i = 0; i < 4; i++) {
            float4 v = x[i];
            v.x *= inv; v.y *= inv; v.z *= inv; v.w *= inv;
            mx[i] = fmax4(mx[i], v);
        }
    }
    float s2 = 0.f;
#pragma unroll
    for (int i = 0; i < 4; i++)
        s2 += mx[i].x * mx[i].x + mx[i].y * mx[i].y + mx[i].z * mx[i].z + mx[i].w * mx[i].w;
    s2 = block_reduce_sum(s2);
    float inv2 = 1.f / fmaxf(sqrtf(s2), 1e-12f);
    float4* out = (float4*)(g_rmaxn + (size_t)bf * Dn);
#pragma unroll
    for (int i = 0; i < 4; i++) {
        float4 v = mx[i];
        v.x *= inv2; v.y *= inv2; v.z *= inv2; v.w *= inv2;
        out[threadIdx.x + i * 256] = v;
    }
}

// ---------------- K_mem_mp (proven at DRAM floor) ----------------
__global__ __launch_bounds__(256) void k_mem_mp(const float* __restrict__ mem1,
                                                const float* __restrict__ mem2) {
    int row = blockIdx.x;
    const float* src = (row >= Mn) ? (mem2 + (size_t)(row - Mn) * ROWn)
                                   : (mem1 + (size_t)row * ROWn);
    float4 mx[4];
#pragma unroll
    for (int i = 0; i < 4; i++) mx[i] = make_float4(-FLT_MAX, -FLT_MAX, -FLT_MAX, -FLT_MAX);
    for (int o = 0; o < OBJn; o++) {
        const float4* p = (const float4*)(src + (size_t)o * Dn);
#pragma unroll
        for (int i = 0; i < 4; i++) mx[i] = fmax4(mx[i], p[threadIdx.x + i * 256]);
    }
    float s = 0.f;
#pragma unroll
    for (int i = 0; i < 4; i++)
        s += mx[i].x * mx[i].x + mx[i].y * mx[i].y + mx[i].z * mx[i].z + mx[i].w * mx[i].w;
    s = block_reduce_sum(s);
    float inv = 1.f / fmaxf(sqrtf(s), 1e-12f);
    float4* out = (float4*)(g_mem_mp + (size_t)row * Dn);
#pragma unroll
    for (int i = 0; i < 4; i++) {
        float4 v = mx[i];
        v.x *= inv; v.y *= inv; v.z *= inv; v.w *= inv;
        out[threadIdx.x + i * 256] = v;
    }
}

// ---------------- K_main: gemm blocks [0,512) + fill blocks [512,1696) ---------------
// gemm: issue-bound (66us). fill: DRAM-bound, now with 4-item load batching so the
// ~80 co-resident fill blocks keep ~1.3 MB in flight and saturate DRAM during gemm.
__global__ __launch_bounds__(256, 4) void k_main(const float* __restrict__ inp,
                                                 float* __restrict__ out) {
    int tid = threadIdx.x;
    if (blockIdx.x < GEMM_BLKS) {
        // ---- gemm v4 (measured 66us standalone; byte-identical) ----
        extern __shared__ float gsm[];
        float* As = gsm;                          // [KCHUNK][81]  [kk][r]
        float* Bs = gsm + KCHUNK * GA_STRIDE;     // [KCHUNK][129] [kk][m]
        int tx = tid & 15;              // m group: 8 each -> 128
        int ty = tid >> 4;              // r group: 5 each -> 80
        int m0 = (blockIdx.x & 15) * 128;
        int ks = blockIdx.x >> 4;
        int kbase = ks * KPER;

        float acc[5][8];
#pragma unroll
        for (int i = 0; i < 5; i++)
#pragma unroll
            for (int j = 0; j < 8; j++) acc[i][j] = 0.f;

        for (int kc = 0; kc < KPER / KCHUNK; kc++) {      // 2 chunks
            int k0 = kbase + kc * KCHUNK;
            __syncthreads();
            for (int idx = tid; idx < 80 * (KCHUNK / 4); idx += 256) {
                int r = idx >> 4, c4 = idx & 15;
                float4 v = *(const float4*)(g_rmaxn + (size_t)r * Dn + k0 + c4 * 4);
                As[(c4 * 4 + 0) * GA_STRIDE + r] = v.x;
                As[(c4 * 4 + 1) * GA_STRIDE + r] = v.y;
                As[(c4 * 4 + 2) * GA_STRIDE + r] = v.z;
                As[(c4 * 4 + 3) * GA_STRIDE + r] = v.w;
            }
#pragma unroll
            for (int l = 0; l < 8; l++) {
                int idx = tid + l * 256;
                int m = idx >> 4, c4 = idx & 15;
                int mg = m0 + m;
                float4 v = make_float4(0.f, 0.f, 0.f, 0.f);
                if (mg < 2 * Mn)
                    v = *(const float4*)(g_mem_mp + (size_t)mg * Dn + k0 + c4 * 4);
                Bs[(c4 * 4 + 0) * GB_STRIDE + m] = v.x;
                Bs[(c4 * 4 + 1) * GB_STRIDE + m] = v.y;
                Bs[(c4 * 4 + 2) * GB_STRIDE + m] = v.z;
                Bs[(c4 * 4 + 3) * GB_STRIDE + m] = v.w;
            }
            __syncthreads();
#pragma unroll 16
            for (int kk = 0; kk < KCHUNK; kk++) {
                float a[5], b[8];
#pragma unroll
                for (int i = 0; i < 5; i++) a[i] = As[kk * GA_STRIDE + ty * 5 + i];
#pragma unroll
                for (int j = 0; j < 8; j++) b[j] = Bs[kk * GB_STRIDE + tx * 8 + j];
#pragma unroll
                for (int i = 0; i < 5; i++)
#pragma unroll
                    for (int j = 0; j < 8; j++) acc[i][j] = fmaf(a[i], b[j], acc[i][j]);
            }
        }
        float* dst = g_partial + (size_t)ks * BFn * MPAD;
#pragma unroll
        for (int i = 0; i < 5; i++) {
            float4* p = (float4*)(dst + (ty * 5 + i) * MPAD + m0 + tx * 8);
            p[0] = make_float4(acc[i][0], acc[i][1], acc[i][2], acc[i][3]);
            p[1] = make_float4(acc[i][4], acc[i][5], acc[i][6], acc[i][7]);
        }
    } else {
        // ---- fill: grid-stride, 4-item ILP batches for DRAM saturation ----
        int fb = blockIdx.x - GEMM_BLKS;
        int nfb = gridDim.x - GEMM_BLKS;
        float4* o4 = (float4*)out;
        const size_t rpn4 = RPN / 4;
        const float4* in4 = (const float4*)inp;
        for (int it0 = fb; it0 < FILL_ITEMS; it0 += 4 * nfb) {
            float4 v[4];
            int bfv[4], chv[4];
            bool ok[4];
#pragma unroll
            for (int u = 0; u < 4; u++) {               // batched independent loads
                int it = it0 + u * nfb;
                ok[u] = (it < FILL_ITEMS);
                int itc = ok[u] ? it : it0;
                bfv[u] = itc / 80;
                chv[u] = itc % 80;
                v[u] = in4[(size_t)bfv[u] * (ROWn / 4) + chv[u] * 256 + tid];
            }
#pragma unroll
            for (int u = 0; u < 4; u++) {
                if (!ok[u]) continue;
                int bf = bfv[u], ch = chv[u];
                int b = bf / Fn, f = bf % Fn;
                int e4 = ch * 256 + tid;
                int oo = e4 >> 10;
                float inv = g_invnorm[bf * OBJn + oo];
                float4 w = v[u];
                w.x *= inv; w.y *= inv; w.z *= inv; w.w *= inv;
#pragma unroll
                for (int q = 0; q < 4; q++) {
                    int lo = g_low[b * 4 + q], hi = g_high[b * 4 + q];
                    size_t ob = ((size_t)((q * Bn + b) * Fn + f)) * (ROWn / 4) + e4;
                    if (f != lo) o4[ob] = w;            // Rp copy
                    if (f != hi) o4[rpn4 + ob] = w;     // Rn copy
                }
            }
        }
    }
}

// ---------------- K_argmax: one block per (row, mem-half) ----------------
__global__ __launch_bounds__(512) void k_argmax() {
    int r = blockIdx.x >> 1;
    int h = blockIdx.x & 1;
    int tid = threadIdx.x;
    float bv = -FLT_MAX;
    int   bm = 0;
    for (int m = tid; m < Mn; m += 512) {
        int mg = h * Mn + m;
        float s = 0.f;
#pragma unroll
        for (int ks = 0; ks < KSPLIT; ks++)
            s += g_partial[(size_t)ks * BFn * MPAD + (size_t)r * MPAD + mg];
        if (s > bv || (s == bv && m < bm)) { bv = s; bm = m; }
    }
    __shared__ float sv[512];
    __shared__ int   sm2[512];
    sv[tid] = bv; sm2[tid] = bm;
    __syncthreads();
    for (int st = 256; st; st >>= 1) {
        if (tid < st) {
            float ov = sv[tid + st]; int om = sm2[tid + st];
            if (ov > sv[tid] || (ov == sv[tid] && om < sm2[tid])) {
                sv[tid] = ov; sm2[tid] = om;
            }
        }
        __syncthreads();
    }
    if (tid == 0) g_sim[h * BFn + r] = sm2[0];
}

// ---------------- K_replace: replaced rows + sim outputs (needs g_sim) ---------------
__global__ __launch_bounds__(256) void k_replace(const float* __restrict__ mem1,
                                                 const float* __restrict__ mem2,
                                                 float* __restrict__ out,
                                                 long long out_size) {
    int t = blockIdx.x;
    if (t == 32) {
        if (blockIdx.y == 0 && threadIdx.x < 16) {
            int bq = threadIdx.x;               // b*4 + q
            int b = bq >> 2, q = bq & 3;
            long long rpn2 = (long long)(2 * RPN);
            if (out_size >= rpn2 + 32) {
                out[(size_t)rpn2 + (q * Bn + b)]      =
                    (float)g_sim[BFn + b * Fn + g_high[bq]];   // high_sim
                out[(size_t)rpn2 + 16 + (q * Bn + b)] =
                    (float)g_sim[b * Fn + g_low[bq]];          // low_sim
            }
        }
        return;
    }
    int which = t & 1;         // 0: Rp/low/mem1   1: Rn/high/mem2
    int bq = t >> 1;           // b*4 + q
    int b = bq >> 2, q = bq & 3;
    int f, row;
    const float* src;
    int lo = g_low[bq];
    if (which == 0) { f = lo;         row = g_sim[b * Fn + lo];       src = mem1; }
    else            { f = g_high[bq]; row = g_sim[BFn + b * Fn + lo]; src = mem2; }
    const float4* s4 = (const float4*)(src + (size_t)row * ROWn);
    float4* d4 = (float4*)(out + (size_t)which * RPN +
                           ((size_t)((q * Bn + b) * Fn + f)) * ROWn);
    int base = blockIdx.y * 1280;              // 16 chunks of 1280 float4
#pragma unroll
    for (int i = 0; i < 5; i++) {
        int e4 = base + threadIdx.x + i * 256;
        d4[e4] = s4[e4];
    }
}

// ---------------- launch: strictly serial, deterministic ----------------
extern "C" void kernel_launch(void* const* d_in, const int* in_sizes, int n_in,
                              void* d_out, int out_size) {
    const float* qr   = (const float*)d_in[0];   // [4,4,20]
    const float* inp  = (const float*)d_in[1];   // [4,20,20,4096]
    const float* mem1 = (const float*)d_in[2];   // [1000,81920]
    const float* mem2 = (const float*)d_in[3];   // [1000,81920]
    const int*   rnd  = (const int*)d_in[4];     // [4,4,1]
    float* out = (float*)d_out;

    // opt into 53.8 KB dynamic smem for k_main (idempotent, capture-safe)
    cudaFuncSetAttribute((const void*)k_main,
                         cudaFuncAttributeMaxDynamicSharedMemorySize, GEMM_SMEM);

    k_sel<<<1, 32>>>(qr, rnd);                               // ~1us
    k_rstats<<<BFn, 256>>>(inp);                             // ~6us
    k_mem_mp<<<2 * Mn, 256>>>(mem1, mem2);                   // ~100us (DRAM floor)
    k_main<<<GEMM_BLKS + FILL_BLKS, 256, GEMM_SMEM>>>(inp, out);  // target ~70us
    k_argmax<<<2 * BFn, 512>>>();                            // ~5us
    k_replace<<<dim3(33, 16), 256>>>(mem1, mem2, out, (long long)out_size);  // ~8us
}